// round 8
// baseline (speedup 1.0000x reference)
#include <cuda_runtime.h>
#include <cuda_bf16.h>

// Scratch (device globals; zero-initialized at module load).
// g_sV0/g_sV1: plain stores (row half-sums), never need re-zeroing — stale
//   values only exist for rows whose sV is never read (U <= 0).
// g_pP/g_pPh: atomic accumulators, re-zeroed each run by the epilogue blocks.
__device__ float g_sV0[8192];
__device__ float g_sV1[8192];
__device__ float g_pP[8192];
__device__ float g_pPh[8192];
__device__ unsigned g_done  = 0;
__device__ unsigned g_done2 = 0;

#define EPI_BLOCKS 32
#define GRID 608            // 4 CTAs x 152 SMs: every SM carries identical load

// Single-launch fused kernel. 3072 tiles of 64KB:
//   tile t -> type = t % 3 (0:W, 1:P, 2:Ph), idx = t / 3.
//   W tile : 8 rows x half-row (2048 cols); warp per row; rows with U<=0
//            skipped (their sV is never consumed).
//   P tile : 16 rows x 1024 cols; 256 thr x float4; atomicAdd partials.
// Cyclic assignment: block b takes t = b + 608*i (5 tiles); the 32 remainder
// tiles go to blocks 576..607. Blocks 0..31 then run the parallel epilogue.
__global__ __launch_bounds__(256, 4)
void fused_kernel(const float* __restrict__ W,  const float* __restrict__ Vn,
                  const float* __restrict__ P,  const float* __restrict__ Ph,
                  const float* __restrict__ pi, const float* __restrict__ C,
                  const float* __restrict__ L,  const float* __restrict__ U,
                  const float* __restrict__ alpha, float* __restrict__ out,
                  int N, int Nnext, int K, int Prows,
                  int nTiles, int full, int extraStart) {
    const int tid = threadIdx.x;
    const int b   = blockIdx.x;

    const int myTiles = full + (b >= extraStart ? 1 : 0);

    // ---------------- matvec phase ----------------
    #pragma unroll 1
    for (int i = 0; i < myTiles; ++i) {
        const int t = (i < full) ? (b + GRID * i) : (GRID * full + (b - extraStart));
        const int type = t % 3;
        const int idx  = t / 3;

        if (type == 0) {
            // ---- W half-row tile: 8 rows x (Nnext/2) cols, warp per row ----
            const int warp = tid >> 5;
            const int lane = tid & 31;
            const int row  = (idx >> 1) * 8 + warp;
            const int half = idx & 1;
            const int hCols = Nnext >> 1;                 // 2048

            const float uval = __ldg(U + row);
            if (uval > 0.0f) {                            // sV needed only if U > 0
                const float4* wr = reinterpret_cast<const float4*>(
                                       W + (size_t)row * Nnext + half * hCols) + lane;
                const float4* vv = reinterpret_cast<const float4*>(
                                       Vn + half * hCols) + lane;
                const int nBatch = hCols / (32 * 4 * 4);  // 2048/512 = 4

                float acc = 0.0f;
                #pragma unroll 1
                for (int it = 0; it < nBatch; ++it) {
                    float4 w0 = __ldg(wr + 0 * 32);
                    float4 w1 = __ldg(wr + 1 * 32);
                    float4 w2 = __ldg(wr + 2 * 32);
                    float4 w3 = __ldg(wr + 3 * 32);
                    float4 v0 = __ldg(vv + 0 * 32);
                    float4 v1 = __ldg(vv + 1 * 32);
                    float4 v2 = __ldg(vv + 2 * 32);
                    float4 v3 = __ldg(vv + 3 * 32);
                    acc = fmaf(w0.x, v0.x, acc); acc = fmaf(w0.y, v0.y, acc);
                    acc = fmaf(w0.z, v0.z, acc); acc = fmaf(w0.w, v0.w, acc);
                    acc = fmaf(w1.x, v1.x, acc); acc = fmaf(w1.y, v1.y, acc);
                    acc = fmaf(w1.z, v1.z, acc); acc = fmaf(w1.w, v1.w, acc);
                    acc = fmaf(w2.x, v2.x, acc); acc = fmaf(w2.y, v2.y, acc);
                    acc = fmaf(w2.z, v2.z, acc); acc = fmaf(w2.w, v2.w, acc);
                    acc = fmaf(w3.x, v3.x, acc); acc = fmaf(w3.y, v3.y, acc);
                    acc = fmaf(w3.z, v3.z, acc); acc = fmaf(w3.w, v3.w, acc);
                    wr += 4 * 32;
                    vv += 4 * 32;
                }
                #pragma unroll
                for (int o = 16; o > 0; o >>= 1)
                    acc += __shfl_down_sync(0xFFFFFFFFu, acc, o);
                if (lane == 0) {
                    if (half) g_sV1[row] = acc; else g_sV0[row] = acc;
                }
            }
        } else {
            // ---- P / P_hat tile: 16 rows x 1024 cols ----
            const float* mat = (type == 1) ? P : Ph;
            float* o_        = (type == 1) ? g_pP : g_pPh;

            const int col = (idx & 1) * 1024 + tid * 4;
            const int r0  = (idx >> 1) * 16;

            const float4* m  = reinterpret_cast<const float4*>(mat + (size_t)r0 * K + col);
            const float4* p4 = reinterpret_cast<const float4*>(pi + r0);
            const size_t  s4 = (size_t)K / 4;

            float4 acc = make_float4(0.f, 0.f, 0.f, 0.f);
            #pragma unroll 1
            for (int rr = 0; rr < 16; rr += 8) {
                float4 w0 = __ldg(m + 0 * s4);
                float4 w1 = __ldg(m + 1 * s4);
                float4 w2 = __ldg(m + 2 * s4);
                float4 w3 = __ldg(m + 3 * s4);
                float4 w4 = __ldg(m + 4 * s4);
                float4 w5 = __ldg(m + 5 * s4);
                float4 w6 = __ldg(m + 6 * s4);
                float4 w7 = __ldg(m + 7 * s4);
                float4 pa = __ldg(p4 + 0);
                float4 pb = __ldg(p4 + 1);

                acc.x = fmaf(pa.x, w0.x, acc.x); acc.y = fmaf(pa.x, w0.y, acc.y);
                acc.z = fmaf(pa.x, w0.z, acc.z); acc.w = fmaf(pa.x, w0.w, acc.w);
                acc.x = fmaf(pa.y, w1.x, acc.x); acc.y = fmaf(pa.y, w1.y, acc.y);
                acc.z = fmaf(pa.y, w1.z, acc.z); acc.w = fmaf(pa.y, w1.w, acc.w);
                acc.x = fmaf(pa.z, w2.x, acc.x); acc.y = fmaf(pa.z, w2.y, acc.y);
                acc.z = fmaf(pa.z, w2.z, acc.z); acc.w = fmaf(pa.z, w2.w, acc.w);
                acc.x = fmaf(pa.w, w3.x, acc.x); acc.y = fmaf(pa.w, w3.y, acc.y);
                acc.z = fmaf(pa.w, w3.z, acc.z); acc.w = fmaf(pa.w, w3.w, acc.w);
                acc.x = fmaf(pb.x, w4.x, acc.x); acc.y = fmaf(pb.x, w4.y, acc.y);
                acc.z = fmaf(pb.x, w4.z, acc.z); acc.w = fmaf(pb.x, w4.w, acc.w);
                acc.x = fmaf(pb.y, w5.x, acc.x); acc.y = fmaf(pb.y, w5.y, acc.y);
                acc.z = fmaf(pb.y, w5.z, acc.z); acc.w = fmaf(pb.y, w5.w, acc.w);
                acc.x = fmaf(pb.z, w6.x, acc.x); acc.y = fmaf(pb.z, w6.y, acc.y);
                acc.z = fmaf(pb.z, w6.z, acc.z); acc.w = fmaf(pb.z, w6.w, acc.w);
                acc.x = fmaf(pb.w, w7.x, acc.x); acc.y = fmaf(pb.w, w7.y, acc.y);
                acc.z = fmaf(pb.w, w7.z, acc.z); acc.w = fmaf(pb.w, w7.w, acc.w);

                m  += 8 * s4;
                p4 += 2;
            }
            atomicAdd(&o_[col + 0], acc.x);
            atomicAdd(&o_[col + 1], acc.y);
            atomicAdd(&o_[col + 2], acc.z);
            atomicAdd(&o_[col + 3], acc.w);
        }
    }

    // ---------------- signal matvec completion ----------------
    __threadfence();
    if (tid == 0) atomicAdd(&g_done, 1u);
    if (b >= EPI_BLOCKS) return;

    // ======== epilogue blocks (b in [0, EPI_BLOCKS)) ========
    // Rank precomputation (depends only on L/U): do it now, hidden in the
    // block-finish spread while other blocks still stream matvec traffic.
    const int sliceLen   = (N + EPI_BLOCKS - 1) / EPI_BLOCKS;   // 128 for N=4096
    const int sliceStart = b * sliceLen;
    const int lane = tid & 31, warp = tid >> 5;

    int pre = 0;
    for (int i = tid; i < sliceStart; i += 256) {
        float li = __ldg(L + i), ui = __ldg(U + i);
        pre += (li < 0.0f && ui > 0.0f);
    }
    #pragma unroll
    for (int o = 16; o > 0; o >>= 1)
        pre += __shfl_down_sync(0xFFFFFFFFu, pre, o);
    __shared__ int wsum[8];
    __shared__ int wcnt[8];
    if (lane == 0) wsum[warp] = pre;
    if (tid < 8) wcnt[tid] = 0;
    __syncthreads();

    const int n = sliceStart + tid;
    float l = 0.f, u = 0.f, c = 0.f;
    bool un = false;
    const bool active = (tid < sliceLen) && (n < N);
    if (active) {
        l = __ldg(L + n); u = __ldg(U + n); c = __ldg(C + n);
        un = (l < 0.0f) && (u > 0.0f);
    }
    unsigned bm = __ballot_sync(0xFFFFFFFFu, un);
    int before = __popc(bm & ((1u << lane) - 1u));
    if (lane == 0) wcnt[warp] = __popc(bm);
    __syncthreads();

    int prefix = 0;
    #pragma unroll
    for (int w = 0; w < 8; ++w) prefix += wsum[w];
    int woff = 0, totalCnt = 0;
    #pragma unroll
    for (int w = 0; w < 8; ++w) {
        woff     += (w < warp) ? wcnt[w] : 0;
        totalCnt += wcnt[w];
    }
    const int k = prefix + woff + before;
    float a_k = 0.0f;
    if (active && un && k < K) a_k = __ldg(alpha + k);

    // ---------------- wait for ALL blocks ----------------
    if (tid == 0) {
        while (atomicAdd(&g_done, 0u) < (unsigned)GRID) __nanosleep(32);
    }
    __syncthreads();
    __threadfence();

    // ---------------- elementwise epilogue (L2-hot) ----------------
    if (active) {
        float val;
        if (un) {
            if (k < K) {
                float sv   = g_sV0[n] + g_sV1[n];
                float vhat = sv - g_pPh[k];
                float rp   = fmaxf(vhat, 0.0f);
                float rn   = fmaxf(-vhat, 0.0f);
                val = rp * u / (u - l) - c - a_k * rn - g_pP[k];
            } else {
                val = 0.0f;
            }
        } else if (u <= 0.0f) {
            val = -c;                              // stably deactivated
        } else if (l >= 0.0f) {
            val = g_sV0[n] + g_sV1[n] - c;         // stably activated
        } else {
            val = 0.0f;
        }
        out[n] = val;
    }

    // ---------------- reset scratch for next graph replay ----------------
    __syncthreads();
    const int zEnd = (b == EPI_BLOCKS - 1) ? K : (prefix + totalCnt);
    for (int i = prefix + tid; i < zEnd; i += 256) {
        g_pP[i]  = 0.0f;
        g_pPh[i] = 0.0f;
    }
    __threadfence();
    if (tid == 0) {
        unsigned d2 = atomicAdd(&g_done2, 1u);
        if (d2 == EPI_BLOCKS - 1) {
            g_done  = 0;
            g_done2 = 0;
            __threadfence();
        }
    }
}

extern "C" void kernel_launch(void* const* d_in, const int* in_sizes, int n_in,
                              void* d_out, int out_size) {
    const float* Vn    = (const float*)d_in[0];   // [N_NEXT]
    const float* W     = (const float*)d_in[1];   // [N_NEXT, N]
    const float* C     = (const float*)d_in[2];   // [N]
    const float* L     = (const float*)d_in[3];   // [N]
    const float* U     = (const float*)d_in[4];   // [N]
    const float* P     = (const float*)d_in[5];   // [P_ROWS, K]
    const float* Ph    = (const float*)d_in[6];   // [P_ROWS, K]
    const float* pi    = (const float*)d_in[7];   // [P_ROWS]
    const float* alpha = (const float*)d_in[8];   // [K]
    float* out = (float*)d_out;

    const int Nnext = in_sizes[0];
    const int N     = in_sizes[2];
    const int Prows = in_sizes[7];
    const int K     = in_sizes[8];

    // 64KB tiles: W = (N/8)*2 half-row tiles; P/Ph = (Prows/16)*(K/1024) each.
    const int nW = (N / 8) * 2;                       // 1024
    const int nP = (Prows / 16) * (K / 1024);         // 1024
    const int nTiles = nW + 2 * nP;                   // 3072
    const int full = nTiles / GRID;                   // 5
    const int rem  = nTiles % GRID;                   // 32
    const int extraStart = GRID - rem;                // blocks 576..607 get one extra

    fused_kernel<<<GRID, 256>>>(W, Vn, P, Ph, pi, C, L, U, alpha, out,
                                N, Nnext, K, Prows, nTiles, full, extraStart);
}

// round 9
// speedup vs baseline: 1.1579x; 1.1579x over previous
#include <cuda_runtime.h>
#include <cuda_bf16.h>

// Scratch (device globals; zero-initialized at module load).
// g_sV: plain stores; stale entries only for rows with U<=0 (never read).
// g_pP/g_pPh: atomic accumulators, re-zeroed each run by epilogue blocks.
__device__ float g_sV[8192];
__device__ float g_pP[8192];
__device__ float g_pPh[8192];
__device__ unsigned g_ticket = 0;  // stolen-unit ticket (offset by NWARPS)
__device__ unsigned g_done   = 0;  // warps finished
__device__ unsigned g_done2  = 0;  // epilogue blocks finished

#define GRID       608             // 4 CTAs x 152 SMs
#define NWARPS     (GRID * 8)      // 4864 warps
#define EPI_BLOCKS 32

// Warp-level work stealing over 12288 uniform 16KB units.
//   unit u: type = u % 3, idx = u / 3  (idx in [0, 4096))
//     type 0: W row idx  — dot(W[idx,:], Vn); skipped when U[idx] <= 0.
//     type 1/2: P / Ph strip — rows [ (idx>>4)*32, +32 ), cols [ (idx&15)*128, +128 )
//               lane handles 4 cols (float4); 4 batches of 8 rows (MLP ~10);
//               4 atomicAdd per lane at the end.
// Each warp: first unit = global warp id (static), then tickets (prefetched).
// No __syncthreads anywhere in the work loop.
__global__ __launch_bounds__(256)
void fused_kernel(const float* __restrict__ W,  const float* __restrict__ Vn,
                  const float* __restrict__ P,  const float* __restrict__ Ph,
                  const float* __restrict__ pi, const float* __restrict__ C,
                  const float* __restrict__ L,  const float* __restrict__ U,
                  const float* __restrict__ alpha, float* __restrict__ out,
                  int N, int Nnext, int K, int Prows, int nUnits) {
    const int tid  = threadIdx.x;
    const int b    = blockIdx.x;
    const int lane = tid & 31;
    const int warp = tid >> 5;
    const int wgid = b * 8 + warp;

    int cur = wgid;                    // static first unit
    for (;;) {
        // prefetch next ticket (latency hidden behind processing of cur)
        unsigned nt = 0;
        if (lane == 0) nt = atomicAdd(&g_ticket, 1u);
        const int next = NWARPS + (int)__shfl_sync(0xFFFFFFFFu, nt, 0);

        // ---- process unit cur ----
        const int type = cur % 3;
        const int idx  = cur / 3;

        if (type == 0) {
            // ---- W row: dot(W[idx,:], Vn) ----
            const int row = idx;
            if (__ldg(U + row) > 0.0f) {           // sV unused when U <= 0
                const float4* wr = reinterpret_cast<const float4*>(W + (size_t)row * Nnext) + lane;
                const float4* vv = reinterpret_cast<const float4*>(Vn) + lane;
                const int nBatch = Nnext / (32 * 4 * 4);   // 8

                float acc = 0.0f;
                #pragma unroll 1
                for (int it = 0; it < nBatch; ++it) {
                    float4 w0 = __ldg(wr + 0 * 32);
                    float4 w1 = __ldg(wr + 1 * 32);
                    float4 w2 = __ldg(wr + 2 * 32);
                    float4 w3 = __ldg(wr + 3 * 32);
                    float4 v0 = __ldg(vv + 0 * 32);
                    float4 v1 = __ldg(vv + 1 * 32);
                    float4 v2 = __ldg(vv + 2 * 32);
                    float4 v3 = __ldg(vv + 3 * 32);
                    acc = fmaf(w0.x, v0.x, acc); acc = fmaf(w0.y, v0.y, acc);
                    acc = fmaf(w0.z, v0.z, acc); acc = fmaf(w0.w, v0.w, acc);
                    acc = fmaf(w1.x, v1.x, acc); acc = fmaf(w1.y, v1.y, acc);
                    acc = fmaf(w1.z, v1.z, acc); acc = fmaf(w1.w, v1.w, acc);
                    acc = fmaf(w2.x, v2.x, acc); acc = fmaf(w2.y, v2.y, acc);
                    acc = fmaf(w2.z, v2.z, acc); acc = fmaf(w2.w, v2.w, acc);
                    acc = fmaf(w3.x, v3.x, acc); acc = fmaf(w3.y, v3.y, acc);
                    acc = fmaf(w3.z, v3.z, acc); acc = fmaf(w3.w, v3.w, acc);
                    wr += 4 * 32;
                    vv += 4 * 32;
                }
                #pragma unroll
                for (int o = 16; o > 0; o >>= 1)
                    acc += __shfl_down_sync(0xFFFFFFFFu, acc, o);
                if (lane == 0) g_sV[row] = acc;
            }
        } else {
            // ---- P / Ph strip: 32 rows x 128 cols ----
            const float* mat = (type == 1) ? P : Ph;
            float* o_        = (type == 1) ? g_pP : g_pPh;

            const int col = (idx & 15) * 128 + lane * 4;
            const int r0  = (idx >> 4) * 32;

            const float4* m  = reinterpret_cast<const float4*>(mat + (size_t)r0 * K + col);
            const float4* p4 = reinterpret_cast<const float4*>(pi + r0);
            const size_t  s4 = (size_t)K / 4;

            float4 acc = make_float4(0.f, 0.f, 0.f, 0.f);
            #pragma unroll 1
            for (int rr = 0; rr < 32; rr += 8) {
                float4 w0 = __ldg(m + 0 * s4);
                float4 w1 = __ldg(m + 1 * s4);
                float4 w2 = __ldg(m + 2 * s4);
                float4 w3 = __ldg(m + 3 * s4);
                float4 w4 = __ldg(m + 4 * s4);
                float4 w5 = __ldg(m + 5 * s4);
                float4 w6 = __ldg(m + 6 * s4);
                float4 w7 = __ldg(m + 7 * s4);
                float4 pa = __ldg(p4 + 0);
                float4 pb = __ldg(p4 + 1);

                acc.x = fmaf(pa.x, w0.x, acc.x); acc.y = fmaf(pa.x, w0.y, acc.y);
                acc.z = fmaf(pa.x, w0.z, acc.z); acc.w = fmaf(pa.x, w0.w, acc.w);
                acc.x = fmaf(pa.y, w1.x, acc.x); acc.y = fmaf(pa.y, w1.y, acc.y);
                acc.z = fmaf(pa.y, w1.z, acc.z); acc.w = fmaf(pa.y, w1.w, acc.w);
                acc.x = fmaf(pa.z, w2.x, acc.x); acc.y = fmaf(pa.z, w2.y, acc.y);
                acc.z = fmaf(pa.z, w2.z, acc.z); acc.w = fmaf(pa.z, w2.w, acc.w);
                acc.x = fmaf(pa.w, w3.x, acc.x); acc.y = fmaf(pa.w, w3.y, acc.y);
                acc.z = fmaf(pa.w, w3.z, acc.z); acc.w = fmaf(pa.w, w3.w, acc.w);
                acc.x = fmaf(pb.x, w4.x, acc.x); acc.y = fmaf(pb.x, w4.y, acc.y);
                acc.z = fmaf(pb.x, w4.z, acc.z); acc.w = fmaf(pb.x, w4.w, acc.w);
                acc.x = fmaf(pb.y, w5.x, acc.x); acc.y = fmaf(pb.y, w5.y, acc.y);
                acc.z = fmaf(pb.y, w5.z, acc.z); acc.w = fmaf(pb.y, w5.w, acc.w);
                acc.x = fmaf(pb.z, w6.x, acc.x); acc.y = fmaf(pb.z, w6.y, acc.y);
                acc.z = fmaf(pb.z, w6.z, acc.z); acc.w = fmaf(pb.z, w6.w, acc.w);
                acc.x = fmaf(pb.w, w7.x, acc.x); acc.y = fmaf(pb.w, w7.y, acc.y);
                acc.z = fmaf(pb.w, w7.z, acc.z); acc.w = fmaf(pb.w, w7.w, acc.w);

                m  += 8 * s4;
                p4 += 2;
            }
            atomicAdd(&o_[col + 0], acc.x);
            atomicAdd(&o_[col + 1], acc.y);
            atomicAdd(&o_[col + 2], acc.z);
            atomicAdd(&o_[col + 3], acc.w);
        }

        if (next >= nUnits) break;
        cur = next;
    }

    // ---------------- signal: this warp is done ----------------
    __threadfence();
    if (lane == 0) atomicAdd(&g_done, 1u);
    if (b >= EPI_BLOCKS) return;

    // ======== epilogue blocks (b in [0, EPI_BLOCKS)) ========
    // Rank precompute depends only on L/U — done while other warps still
    // stream matvec traffic (hidden in the finish spread).
    const int sliceLen   = (N + EPI_BLOCKS - 1) / EPI_BLOCKS;   // 128 @ N=4096
    const int sliceStart = b * sliceLen;

    __syncthreads();   // all 8 warps of this block are out of the work loop

    int pre = 0;
    for (int i = tid; i < sliceStart; i += 256) {
        float li = __ldg(L + i), ui = __ldg(U + i);
        pre += (li < 0.0f && ui > 0.0f);
    }
    #pragma unroll
    for (int o = 16; o > 0; o >>= 1)
        pre += __shfl_down_sync(0xFFFFFFFFu, pre, o);
    __shared__ int wsum[8];
    __shared__ int wcnt[8];
    if (lane == 0) wsum[warp] = pre;
    if (tid < 8) wcnt[tid] = 0;
    __syncthreads();

    const int n = sliceStart + tid;
    float l = 0.f, u = 0.f, c = 0.f;
    bool un = false;
    const bool active = (tid < sliceLen) && (n < N);
    if (active) {
        l = __ldg(L + n); u = __ldg(U + n); c = __ldg(C + n);
        un = (l < 0.0f) && (u > 0.0f);
    }
    unsigned bm = __ballot_sync(0xFFFFFFFFu, un);
    int before = __popc(bm & ((1u << lane) - 1u));
    if (lane == 0) wcnt[warp] = __popc(bm);
    __syncthreads();

    int prefix = 0;
    #pragma unroll
    for (int w = 0; w < 8; ++w) prefix += wsum[w];
    int woff = 0, totalCnt = 0;
    #pragma unroll
    for (int w = 0; w < 8; ++w) {
        woff     += (w < warp) ? wcnt[w] : 0;
        totalCnt += wcnt[w];
    }
    const int k = prefix + woff + before;
    float a_k = 0.0f;
    if (active && un && k < K) a_k = __ldg(alpha + k);

    // ---------------- wait for ALL warps ----------------
    if (tid == 0) {
        while (atomicAdd(&g_done, 0u) < (unsigned)NWARPS) __nanosleep(32);
    }
    __syncthreads();
    __threadfence();

    // ---------------- elementwise epilogue (L2-hot) ----------------
    if (active) {
        float val;
        if (un) {
            if (k < K) {
                float vhat = g_sV[n] - g_pPh[k];
                float rp   = fmaxf(vhat, 0.0f);
                float rn   = fmaxf(-vhat, 0.0f);
                val = rp * u / (u - l) - c - a_k * rn - g_pP[k];
            } else {
                val = 0.0f;
            }
        } else if (u <= 0.0f) {
            val = -c;                  // stably deactivated
        } else if (l >= 0.0f) {
            val = g_sV[n] - c;         // stably activated
        } else {
            val = 0.0f;
        }
        out[n] = val;
    }

    // ---------------- reset scratch for next graph replay ----------------
    __syncthreads();
    const int zEnd = (b == EPI_BLOCKS - 1) ? K : (prefix + totalCnt);
    for (int i = prefix + tid; i < zEnd; i += 256) {
        g_pP[i]  = 0.0f;
        g_pPh[i] = 0.0f;
    }
    __threadfence();
    if (tid == 0) {
        unsigned d2 = atomicAdd(&g_done2, 1u);
        if (d2 == EPI_BLOCKS - 1) {    // very last epilogue block resets counters
            g_ticket = 0;
            g_done   = 0;
            g_done2  = 0;
            __threadfence();
        }
    }
}

extern "C" void kernel_launch(void* const* d_in, const int* in_sizes, int n_in,
                              void* d_out, int out_size) {
    const float* Vn    = (const float*)d_in[0];   // [N_NEXT]
    const float* W     = (const float*)d_in[1];   // [N_NEXT, N]
    const float* C     = (const float*)d_in[2];   // [N]
    const float* L     = (const float*)d_in[3];   // [N]
    const float* U     = (const float*)d_in[4];   // [N]
    const float* P     = (const float*)d_in[5];   // [P_ROWS, K]
    const float* Ph    = (const float*)d_in[6];   // [P_ROWS, K]
    const float* pi    = (const float*)d_in[7];   // [P_ROWS]
    const float* alpha = (const float*)d_in[8];   // [K]
    float* out = (float*)d_out;

    const int Nnext = in_sizes[0];
    const int N     = in_sizes[2];
    const int Prows = in_sizes[7];
    const int K     = in_sizes[8];

    // 16KB units: N W-rows + 2 * (Prows/32)*(K/128) P strips = 12288
    const int nUnits = N + 2 * (Prows / 32) * (K / 128);

    fused_kernel<<<GRID, 256>>>(W, Vn, P, Ph, pi, C, L, U, alpha, out,
                                N, Nnext, K, Prows, nUnits);
}

// round 10
// speedup vs baseline: 1.1744x; 1.0142x over previous
#include <cuda_runtime.h>
#include <cuda_bf16.h>

// Scratch (device globals; zero-initialized at module load).
// g_sV: plain stores, fully overwritten each run.
// g_pP/g_pPh: atomic accumulators, re-zeroed each run by epilogue blocks.
__device__ float g_sV[8192];
__device__ float g_pP[8192];
__device__ float g_pPh[8192];
__device__ unsigned g_done  = 0;
__device__ unsigned g_done2 = 0;

#define GRID       1024
#define THREADS    128
#define EPI_BLOCKS 32

// Single-launch fused kernel, static balanced tiling at fine CTA granularity.
// 3072 tiles of 64KB: tile t -> type = t % 3 (0:W, 1:P, 2:Ph), idx = t / 3.
// Block b (of 1024, 128 threads) handles tiles {b, b+1024, b+2048}; since
// 1024 % 3 == 1 every block gets exactly one tile of each type -> identical
// 192KB of traffic per block. 1024 CTAs over 152 SMs quantizes to 6 or 7
// CTAs/SM (96% balance vs 84% at 512 CTAs).
//   W tile : 4 rows x 4096 cols, warp per row, MLP~8 float4 batches.
//   P tile : 32 rows x 512 cols, thread = 4 cols, 4 batches of 8 rows, atomics.
// Blocks 0..31 additionally run the epilogue (rank precompute hidden in the
// block-finish spread, then spin, then elementwise writes from L2-hot scratch).
__global__ __launch_bounds__(THREADS)
void fused_kernel(const float* __restrict__ W,  const float* __restrict__ Vn,
                  const float* __restrict__ P,  const float* __restrict__ Ph,
                  const float* __restrict__ pi, const float* __restrict__ C,
                  const float* __restrict__ L,  const float* __restrict__ U,
                  const float* __restrict__ alpha, float* __restrict__ out,
                  int N, int Nnext, int K, int Prows) {
    const int tid  = threadIdx.x;
    const int b    = blockIdx.x;
    const int lane = tid & 31;
    const int warp = tid >> 5;          // [0,4)

    // ---------------- matvec phase: 3 static tiles ----------------
    #pragma unroll 1
    for (int i = 0; i < 3; ++i) {
        const int t    = b + GRID * i;
        const int type = t % 3;
        const int idx  = t / 3;         // [0, 1024)

        if (type == 0) {
            // ---- W tile: 4 rows, warp per row, full 4096 cols ----
            const int row = idx * 4 + warp;

            const float4* wr = reinterpret_cast<const float4*>(W + (size_t)row * Nnext) + lane;
            const float4* vv = reinterpret_cast<const float4*>(Vn) + lane;
            const int nBatch = Nnext / (32 * 4 * 4);      // 4096/512 = 8

            float acc = 0.0f;
            #pragma unroll 1
            for (int it = 0; it < nBatch; ++it) {
                float4 w0 = __ldg(wr + 0 * 32);
                float4 w1 = __ldg(wr + 1 * 32);
                float4 w2 = __ldg(wr + 2 * 32);
                float4 w3 = __ldg(wr + 3 * 32);
                float4 v0 = __ldg(vv + 0 * 32);
                float4 v1 = __ldg(vv + 1 * 32);
                float4 v2 = __ldg(vv + 2 * 32);
                float4 v3 = __ldg(vv + 3 * 32);
                acc = fmaf(w0.x, v0.x, acc); acc = fmaf(w0.y, v0.y, acc);
                acc = fmaf(w0.z, v0.z, acc); acc = fmaf(w0.w, v0.w, acc);
                acc = fmaf(w1.x, v1.x, acc); acc = fmaf(w1.y, v1.y, acc);
                acc = fmaf(w1.z, v1.z, acc); acc = fmaf(w1.w, v1.w, acc);
                acc = fmaf(w2.x, v2.x, acc); acc = fmaf(w2.y, v2.y, acc);
                acc = fmaf(w2.z, v2.z, acc); acc = fmaf(w2.w, v2.w, acc);
                acc = fmaf(w3.x, v3.x, acc); acc = fmaf(w3.y, v3.y, acc);
                acc = fmaf(w3.z, v3.z, acc); acc = fmaf(w3.w, v3.w, acc);
                wr += 4 * 32;
                vv += 4 * 32;
            }
            #pragma unroll
            for (int o = 16; o > 0; o >>= 1)
                acc += __shfl_down_sync(0xFFFFFFFFu, acc, o);
            if (lane == 0) g_sV[row] = acc;
        } else {
            // ---- P / P_hat tile: 32 rows x 512 cols ----
            const float* mat = (type == 1) ? P : Ph;
            float* o_        = (type == 1) ? g_pP : g_pPh;

            const int col = (idx & 3) * 512 + tid * 4;    // 128 thr x 4 = 512 cols
            const int r0  = (idx >> 2) * 32;

            const float4* m  = reinterpret_cast<const float4*>(mat + (size_t)r0 * K + col);
            const float4* p4 = reinterpret_cast<const float4*>(pi + r0);
            const size_t  s4 = (size_t)K / 4;

            float4 acc = make_float4(0.f, 0.f, 0.f, 0.f);
            #pragma unroll 1
            for (int rr = 0; rr < 32; rr += 8) {
                float4 w0 = __ldg(m + 0 * s4);
                float4 w1 = __ldg(m + 1 * s4);
                float4 w2 = __ldg(m + 2 * s4);
                float4 w3 = __ldg(m + 3 * s4);
                float4 w4 = __ldg(m + 4 * s4);
                float4 w5 = __ldg(m + 5 * s4);
                float4 w6 = __ldg(m + 6 * s4);
                float4 w7 = __ldg(m + 7 * s4);
                float4 pa = __ldg(p4 + 0);
                float4 pb = __ldg(p4 + 1);

                acc.x = fmaf(pa.x, w0.x, acc.x); acc.y = fmaf(pa.x, w0.y, acc.y);
                acc.z = fmaf(pa.x, w0.z, acc.z); acc.w = fmaf(pa.x, w0.w, acc.w);
                acc.x = fmaf(pa.y, w1.x, acc.x); acc.y = fmaf(pa.y, w1.y, acc.y);
                acc.z = fmaf(pa.y, w1.z, acc.z); acc.w = fmaf(pa.y, w1.w, acc.w);
                acc.x = fmaf(pa.z, w2.x, acc.x); acc.y = fmaf(pa.z, w2.y, acc.y);
                acc.z = fmaf(pa.z, w2.z, acc.z); acc.w = fmaf(pa.z, w2.w, acc.w);
                acc.x = fmaf(pa.w, w3.x, acc.x); acc.y = fmaf(pa.w, w3.y, acc.y);
                acc.z = fmaf(pa.w, w3.z, acc.z); acc.w = fmaf(pa.w, w3.w, acc.w);
                acc.x = fmaf(pb.x, w4.x, acc.x); acc.y = fmaf(pb.x, w4.y, acc.y);
                acc.z = fmaf(pb.x, w4.z, acc.z); acc.w = fmaf(pb.x, w4.w, acc.w);
                acc.x = fmaf(pb.y, w5.x, acc.x); acc.y = fmaf(pb.y, w5.y, acc.y);
                acc.z = fmaf(pb.y, w5.z, acc.z); acc.w = fmaf(pb.y, w5.w, acc.w);
                acc.x = fmaf(pb.z, w6.x, acc.x); acc.y = fmaf(pb.z, w6.y, acc.y);
                acc.z = fmaf(pb.z, w6.z, acc.z); acc.w = fmaf(pb.z, w6.w, acc.w);
                acc.x = fmaf(pb.w, w7.x, acc.x); acc.y = fmaf(pb.w, w7.y, acc.y);
                acc.z = fmaf(pb.w, w7.z, acc.z); acc.w = fmaf(pb.w, w7.w, acc.w);

                m  += 8 * s4;
                p4 += 2;
            }
            atomicAdd(&o_[col + 0], acc.x);
            atomicAdd(&o_[col + 1], acc.y);
            atomicAdd(&o_[col + 2], acc.z);
            atomicAdd(&o_[col + 3], acc.w);
        }
    }

    // ---------------- signal matvec completion (race-safe) ----------------
    __syncthreads();                 // all warps of this block finished stores
    __threadfence();
    if (tid == 0) atomicAdd(&g_done, 1u);
    if (b >= EPI_BLOCKS) return;

    // ======== epilogue blocks (b in [0, EPI_BLOCKS)) ========
    // Rank precompute (depends only on L/U) — hidden in the finish spread.
    const int sliceLen   = (N + EPI_BLOCKS - 1) / EPI_BLOCKS;   // 128 @ N=4096
    const int sliceStart = b * sliceLen;

    int pre = 0;
    for (int i = tid; i < sliceStart; i += THREADS) {
        float li = __ldg(L + i), ui = __ldg(U + i);
        pre += (li < 0.0f && ui > 0.0f);
    }
    #pragma unroll
    for (int o = 16; o > 0; o >>= 1)
        pre += __shfl_down_sync(0xFFFFFFFFu, pre, o);
    __shared__ int wsum[4];
    __shared__ int wcnt[4];
    if (lane == 0) wsum[warp] = pre;
    if (tid < 4) wcnt[tid] = 0;
    __syncthreads();

    const int n = sliceStart + tid;           // one neuron per thread
    float l = 0.f, u = 0.f, c = 0.f;
    bool un = false;
    const bool active = (tid < sliceLen) && (n < N);
    if (active) {
        l = __ldg(L + n); u = __ldg(U + n); c = __ldg(C + n);
        un = (l < 0.0f) && (u > 0.0f);
    }
    unsigned bm = __ballot_sync(0xFFFFFFFFu, un);
    int before = __popc(bm & ((1u << lane) - 1u));
    if (lane == 0) wcnt[warp] = __popc(bm);
    __syncthreads();

    int prefix = 0;
    #pragma unroll
    for (int w = 0; w < 4; ++w) prefix += wsum[w];
    int woff = 0, totalCnt = 0;
    #pragma unroll
    for (int w = 0; w < 4; ++w) {
        woff     += (w < warp) ? wcnt[w] : 0;
        totalCnt += wcnt[w];
    }
    const int k = prefix + woff + before;
    float a_k = 0.0f;
    if (active && un && k < K) a_k = __ldg(alpha + k);

    // ---------------- wait for ALL blocks ----------------
    if (tid == 0) {
        while (atomicAdd(&g_done, 0u) < (unsigned)GRID) __nanosleep(32);
    }
    __syncthreads();
    __threadfence();

    // ---------------- elementwise epilogue (L2-hot) ----------------
    if (active) {
        float val;
        if (un) {
            if (k < K) {
                float vhat = g_sV[n] - g_pPh[k];
                float rp   = fmaxf(vhat, 0.0f);
                float rn   = fmaxf(-vhat, 0.0f);
                val = rp * u / (u - l) - c - a_k * rn - g_pP[k];
            } else {
                val = 0.0f;
            }
        } else if (u <= 0.0f) {
            val = -c;                  // stably deactivated
        } else if (l >= 0.0f) {
            val = g_sV[n] - c;         // stably activated
        } else {
            val = 0.0f;
        }
        out[n] = val;
    }

    // ---------------- reset scratch for next graph replay ----------------
    __syncthreads();
    const int zEnd = (b == EPI_BLOCKS - 1) ? K : (prefix + totalCnt);
    for (int i = prefix + tid; i < zEnd; i += THREADS) {
        g_pP[i]  = 0.0f;
        g_pPh[i] = 0.0f;
    }
    __threadfence();
    if (tid == 0) {
        unsigned d2 = atomicAdd(&g_done2, 1u);
        if (d2 == EPI_BLOCKS - 1) {   // very last epilogue block resets counters
            g_done  = 0;
            g_done2 = 0;
            __threadfence();
        }
    }
}

extern "C" void kernel_launch(void* const* d_in, const int* in_sizes, int n_in,
                              void* d_out, int out_size) {
    const float* Vn    = (const float*)d_in[0];   // [N_NEXT]
    const float* W     = (const float*)d_in[1];   // [N_NEXT, N]
    const float* C     = (const float*)d_in[2];   // [N]
    const float* L     = (const float*)d_in[3];   // [N]
    const float* U     = (const float*)d_in[4];   // [N]
    const float* P     = (const float*)d_in[5];   // [P_ROWS, K]
    const float* Ph    = (const float*)d_in[6];   // [P_ROWS, K]
    const float* pi    = (const float*)d_in[7];   // [P_ROWS]
    const float* alpha = (const float*)d_in[8];   // [K]
    float* out = (float*)d_out;

    const int Nnext = in_sizes[0];
    const int N     = in_sizes[2];
    const int Prows = in_sizes[7];
    const int K     = in_sizes[8];

    // GRID=1024, 3072 x 64KB tiles: W = N/4, P = Ph = (Prows/32)*(K/512) = 1024 each
    fused_kernel<<<GRID, THREADS>>>(W, Vn, P, Ph, pi, C, L, U, alpha, out,
                                    N, Nnext, K, Prows);
}

// round 11
// speedup vs baseline: 1.1808x; 1.0055x over previous
#include <cuda_runtime.h>
#include <cuda_bf16.h>

// Scratch (device globals; zero-initialized at module load).
// g_sV: plain stores; stale entries only for rows with U<=0 (never read).
// g_pP/g_pPh: atomic accumulators, re-zeroed each run by epilogue blocks.
__device__ float g_sV[8192];
__device__ float g_pP[8192];
__device__ float g_pPh[8192];
__device__ unsigned g_done  = 0;
__device__ unsigned g_done2 = 0;

#define EPI_BLOCKS 32
#define GRID       512

// Single-launch fused kernel, static balanced tiling (R7 structure).
// Grid = 512 blocks x 256 threads, 1536 tiles of ~128KB:
//   tile t -> type = t % 3 (0:W, 1:P, 2:Ph), idx = t / 3.
//   Block b handles tiles {b, b+512, b+1024}: exactly one tile of each type.
// W tile: 8 STRIDED rows {idx + 512*j}, warp j per row; rows with U <= 0 are
//   skipped (their sV is never consumed). Striding maps the contiguous
//   deactivated band onto the same warps of every tile -> balance preserved.
// P tile: 32 rows x 1024 cols, 256 thr x float4, MLP~10, atomicAdd partials.
// Blocks 0..31 run the parallel epilogue in-kernel (rank precompute hidden in
// the block-finish spread, spin on done counter, L2-hot elementwise writes).
__global__ __launch_bounds__(256, 4)
void fused_kernel(const float* __restrict__ W,  const float* __restrict__ Vn,
                  const float* __restrict__ P,  const float* __restrict__ Ph,
                  const float* __restrict__ pi, const float* __restrict__ C,
                  const float* __restrict__ L,  const float* __restrict__ U,
                  const float* __restrict__ alpha, float* __restrict__ out,
                  int N, int Nnext, int K, int Prows) {
    const int tid  = threadIdx.x;
    const int b    = blockIdx.x;
    const int lane = tid & 31;
    const int warp = tid >> 5;           // [0,8)

    // ---------------- matvec phase: 3 static tiles ----------------
    #pragma unroll 1
    for (int i = 0; i < 3; ++i) {
        const int t    = b + GRID * i;
        const int type = t % 3;
        const int idx  = t / 3;          // [0, 512)

        if (type == 0) {
            // ---- W tile: 8 strided rows, warp j <- row idx + 512*j ----
            const int row = idx + (N >> 3) * warp;          // N/8 = 512

            if (__ldg(U + row) > 0.0f) {                    // sV unused if U <= 0
                const float4* wr = reinterpret_cast<const float4*>(W + (size_t)row * Nnext) + lane;
                const float4* vv = reinterpret_cast<const float4*>(Vn) + lane;
                const int nBatch = Nnext / (32 * 4 * 4);    // 4096/512 = 8

                float acc = 0.0f;
                #pragma unroll 1
                for (int it = 0; it < nBatch; ++it) {
                    float4 w0 = __ldg(wr + 0 * 32);
                    float4 w1 = __ldg(wr + 1 * 32);
                    float4 w2 = __ldg(wr + 2 * 32);
                    float4 w3 = __ldg(wr + 3 * 32);
                    float4 v0 = __ldg(vv + 0 * 32);
                    float4 v1 = __ldg(vv + 1 * 32);
                    float4 v2 = __ldg(vv + 2 * 32);
                    float4 v3 = __ldg(vv + 3 * 32);
                    acc = fmaf(w0.x, v0.x, acc); acc = fmaf(w0.y, v0.y, acc);
                    acc = fmaf(w0.z, v0.z, acc); acc = fmaf(w0.w, v0.w, acc);
                    acc = fmaf(w1.x, v1.x, acc); acc = fmaf(w1.y, v1.y, acc);
                    acc = fmaf(w1.z, v1.z, acc); acc = fmaf(w1.w, v1.w, acc);
                    acc = fmaf(w2.x, v2.x, acc); acc = fmaf(w2.y, v2.y, acc);
                    acc = fmaf(w2.z, v2.z, acc); acc = fmaf(w2.w, v2.w, acc);
                    acc = fmaf(w3.x, v3.x, acc); acc = fmaf(w3.y, v3.y, acc);
                    acc = fmaf(w3.z, v3.z, acc); acc = fmaf(w3.w, v3.w, acc);
                    wr += 4 * 32;
                    vv += 4 * 32;
                }
                #pragma unroll
                for (int o = 16; o > 0; o >>= 1)
                    acc += __shfl_down_sync(0xFFFFFFFFu, acc, o);
                if (lane == 0) g_sV[row] = acc;
            }
        } else {
            // ---- P / P_hat tile: 32 rows x 1024 cols ----
            const float* mat = (type == 1) ? P : Ph;
            float* o_        = (type == 1) ? g_pP : g_pPh;

            const int col = (idx & 1) * 1024 + tid * 4;
            const int r0  = (idx >> 1) * 32;

            const float4* m  = reinterpret_cast<const float4*>(mat + (size_t)r0 * K + col);
            const float4* p4 = reinterpret_cast<const float4*>(pi + r0);
            const size_t  s4 = (size_t)K / 4;

            float4 acc = make_float4(0.f, 0.f, 0.f, 0.f);
            #pragma unroll 1
            for (int rr = 0; rr < 32; rr += 8) {
                float4 w0 = __ldg(m + 0 * s4);
                float4 w1 = __ldg(m + 1 * s4);
                float4 w2 = __ldg(m + 2 * s4);
                float4 w3 = __ldg(m + 3 * s4);
                float4 w4 = __ldg(m + 4 * s4);
                float4 w5 = __ldg(m + 5 * s4);
                float4 w6 = __ldg(m + 6 * s4);
                float4 w7 = __ldg(m + 7 * s4);
                float4 pa = __ldg(p4 + 0);
                float4 pb = __ldg(p4 + 1);

                acc.x = fmaf(pa.x, w0.x, acc.x); acc.y = fmaf(pa.x, w0.y, acc.y);
                acc.z = fmaf(pa.x, w0.z, acc.z); acc.w = fmaf(pa.x, w0.w, acc.w);
                acc.x = fmaf(pa.y, w1.x, acc.x); acc.y = fmaf(pa.y, w1.y, acc.y);
                acc.z = fmaf(pa.y, w1.z, acc.z); acc.w = fmaf(pa.y, w1.w, acc.w);
                acc.x = fmaf(pa.z, w2.x, acc.x); acc.y = fmaf(pa.z, w2.y, acc.y);
                acc.z = fmaf(pa.z, w2.z, acc.z); acc.w = fmaf(pa.z, w2.w, acc.w);
                acc.x = fmaf(pa.w, w3.x, acc.x); acc.y = fmaf(pa.w, w3.y, acc.y);
                acc.z = fmaf(pa.w, w3.z, acc.z); acc.w = fmaf(pa.w, w3.w, acc.w);
                acc.x = fmaf(pb.x, w4.x, acc.x); acc.y = fmaf(pb.x, w4.y, acc.y);
                acc.z = fmaf(pb.x, w4.z, acc.z); acc.w = fmaf(pb.x, w4.w, acc.w);
                acc.x = fmaf(pb.y, w5.x, acc.x); acc.y = fmaf(pb.y, w5.y, acc.y);
                acc.z = fmaf(pb.y, w5.z, acc.z); acc.w = fmaf(pb.y, w5.w, acc.w);
                acc.x = fmaf(pb.z, w6.x, acc.x); acc.y = fmaf(pb.z, w6.y, acc.y);
                acc.z = fmaf(pb.z, w6.z, acc.z); acc.w = fmaf(pb.z, w6.w, acc.w);
                acc.x = fmaf(pb.w, w7.x, acc.x); acc.y = fmaf(pb.w, w7.y, acc.y);
                acc.z = fmaf(pb.w, w7.z, acc.z); acc.w = fmaf(pb.w, w7.w, acc.w);

                m  += 8 * s4;
                p4 += 2;
            }
            atomicAdd(&o_[col + 0], acc.x);
            atomicAdd(&o_[col + 1], acc.y);
            atomicAdd(&o_[col + 2], acc.z);
            atomicAdd(&o_[col + 3], acc.w);
        }
    }

    // ---------------- signal matvec completion (race-safe) ----------------
    __syncthreads();               // all warps of this block done with stores
    __threadfence();
    if (tid == 0) atomicAdd(&g_done, 1u);
    if (b >= EPI_BLOCKS) return;

    // ======== epilogue blocks (b in [0, EPI_BLOCKS)) ========
    // Rank precompute (depends only on L/U) — hidden in the finish spread.
    const int sliceLen   = (N + EPI_BLOCKS - 1) / EPI_BLOCKS;   // 128 @ N=4096
    const int sliceStart = b * sliceLen;

    int pre = 0;
    for (int i = tid; i < sliceStart; i += 256) {
        float li = __ldg(L + i), ui = __ldg(U + i);
        pre += (li < 0.0f && ui > 0.0f);
    }
    #pragma unroll
    for (int o = 16; o > 0; o >>= 1)
        pre += __shfl_down_sync(0xFFFFFFFFu, pre, o);
    __shared__ int wsum[8];
    __shared__ int wcnt[8];
    if (lane == 0) wsum[warp] = pre;
    if (tid < 8) wcnt[tid] = 0;
    __syncthreads();

    const int n = sliceStart + tid;          // one neuron per thread (tid<128)
    float l = 0.f, u = 0.f, c = 0.f;
    bool un = false;
    const bool active = (tid < sliceLen) && (n < N);
    if (active) {
        l = __ldg(L + n); u = __ldg(U + n); c = __ldg(C + n);
        un = (l < 0.0f) && (u > 0.0f);
    }
    unsigned bm = __ballot_sync(0xFFFFFFFFu, un);
    int before = __popc(bm & ((1u << lane) - 1u));
    if (lane == 0) wcnt[warp] = __popc(bm);
    __syncthreads();

    int prefix = 0;
    #pragma unroll
    for (int w = 0; w < 8; ++w) prefix += wsum[w];
    int woff = 0, totalCnt = 0;
    #pragma unroll
    for (int w = 0; w < 8; ++w) {
        woff     += (w < warp) ? wcnt[w] : 0;
        totalCnt += wcnt[w];
    }
    const int k = prefix + woff + before;
    float a_k = 0.0f;
    if (active && un && k < K) a_k = __ldg(alpha + k);

    // ---------------- wait for ALL blocks ----------------
    if (tid == 0) {
        while (atomicAdd(&g_done, 0u) < (unsigned)GRID) __nanosleep(32);
    }
    __syncthreads();
    __threadfence();

    // ---------------- elementwise epilogue (L2-hot) ----------------
    if (active) {
        float val;
        if (un) {
            if (k < K) {
                float vhat = g_sV[n] - g_pPh[k];
                float rp   = fmaxf(vhat, 0.0f);
                float rn   = fmaxf(-vhat, 0.0f);
                val = rp * u / (u - l) - c - a_k * rn - g_pP[k];
            } else {
                val = 0.0f;
            }
        } else if (u <= 0.0f) {
            val = -c;                  // stably deactivated (sV never needed)
        } else if (l >= 0.0f) {
            val = g_sV[n] - c;         // stably activated
        } else {
            val = 0.0f;
        }
        out[n] = val;
    }

    // ---------------- reset scratch for next graph replay ----------------
    __syncthreads();
    const int zEnd = (b == EPI_BLOCKS - 1) ? K : (prefix + totalCnt);
    for (int i = prefix + tid; i < zEnd; i += 256) {
        g_pP[i]  = 0.0f;
        g_pPh[i] = 0.0f;
    }
    __threadfence();
    if (tid == 0) {
        unsigned d2 = atomicAdd(&g_done2, 1u);
        if (d2 == EPI_BLOCKS - 1) {   // very last epilogue block resets counters
            g_done  = 0;
            g_done2 = 0;
            __threadfence();
        }
    }
}

extern "C" void kernel_launch(void* const* d_in, const int* in_sizes, int n_in,
                              void* d_out, int out_size) {
    const float* Vn    = (const float*)d_in[0];   // [N_NEXT]
    const float* W     = (const float*)d_in[1];   // [N_NEXT, N]
    const float* C     = (const float*)d_in[2];   // [N]
    const float* L     = (const float*)d_in[3];   // [N]
    const float* U     = (const float*)d_in[4];   // [N]
    const float* P     = (const float*)d_in[5];   // [P_ROWS, K]
    const float* Ph    = (const float*)d_in[6];   // [P_ROWS, K]
    const float* pi    = (const float*)d_in[7];   // [P_ROWS]
    const float* alpha = (const float*)d_in[8];   // [K]
    float* out = (float*)d_out;

    const int Nnext = in_sizes[0];
    const int N     = in_sizes[2];
    const int Prows = in_sizes[7];
    const int K     = in_sizes[8];

    fused_kernel<<<GRID, 256>>>(W, Vn, P, Ph, pi, C, L, U, alpha, out,
                                N, Nnext, K, Prows);
}

// round 12
// speedup vs baseline: 1.1905x; 1.0083x over previous
#include <cuda_runtime.h>
#include <cuda_bf16.h>

// Scratch (device globals; zero-initialized at module load).
// g_sV: plain stores; stale entries only for rows with U<=0 (never read).
// g_pP/g_pPh: atomic accumulators, re-zeroed each run by epilogue blocks.
__device__ float g_sV[8192];
__device__ float g_pP[8192];
__device__ float g_pPh[8192];
__device__ unsigned g_done  = 0;
__device__ unsigned g_done2 = 0;

#define EPI_BLOCKS 64
#define GRID       512

// Single-launch fused kernel, static balanced tiling.
// Grid = 512 blocks x 256 threads, 1536 tiles of ~128KB:
//   tile t -> type = t % 3 (0:W, 1:P, 2:Ph), idx = t / 3.
//   Block b handles tiles {b, b+512, b+1024}: exactly one tile of each type.
// W tile: 8 STRIDED rows {idx + 512*j}, warp j per row; rows with U <= 0 are
//   skipped (their sV is never consumed); striding keeps blocks balanced.
// P tile: 32 rows x 1024 cols, 256 thr x float4, MLP~10, atomicAdd partials.
// All read-once matrix traffic uses __ldcs (evict-first) to keep L2 from
// churning on dead lines; reused operands (Vn, pi, scratch) stay cached.
// Blocks 0..63 run the parallel epilogue in-kernel.
__global__ __launch_bounds__(256, 4)
void fused_kernel(const float* __restrict__ W,  const float* __restrict__ Vn,
                  const float* __restrict__ P,  const float* __restrict__ Ph,
                  const float* __restrict__ pi, const float* __restrict__ C,
                  const float* __restrict__ L,  const float* __restrict__ U,
                  const float* __restrict__ alpha, float* __restrict__ out,
                  int N, int Nnext, int K, int Prows) {
    const int tid  = threadIdx.x;
    const int b    = blockIdx.x;
    const int lane = tid & 31;
    const int warp = tid >> 5;           // [0,8)

    // ---------------- matvec phase: 3 static tiles ----------------
    #pragma unroll 1
    for (int i = 0; i < 3; ++i) {
        const int t    = b + GRID * i;
        const int type = t % 3;
        const int idx  = t / 3;          // [0, 512)

        if (type == 0) {
            // ---- W tile: 8 strided rows, warp j <- row idx + 512*j ----
            const int row = idx + (N >> 3) * warp;          // N/8 = 512

            if (__ldg(U + row) > 0.0f) {                    // sV unused if U <= 0
                const float4* wr = reinterpret_cast<const float4*>(W + (size_t)row * Nnext) + lane;
                const float4* vv = reinterpret_cast<const float4*>(Vn) + lane;
                const int nBatch = Nnext / (32 * 4 * 4);    // 4096/512 = 8

                float acc = 0.0f;
                #pragma unroll 1
                for (int it = 0; it < nBatch; ++it) {
                    float4 w0 = __ldcs(wr + 0 * 32);
                    float4 w1 = __ldcs(wr + 1 * 32);
                    float4 w2 = __ldcs(wr + 2 * 32);
                    float4 w3 = __ldcs(wr + 3 * 32);
                    float4 v0 = __ldg(vv + 0 * 32);
                    float4 v1 = __ldg(vv + 1 * 32);
                    float4 v2 = __ldg(vv + 2 * 32);
                    float4 v3 = __ldg(vv + 3 * 32);
                    acc = fmaf(w0.x, v0.x, acc); acc = fmaf(w0.y, v0.y, acc);
                    acc = fmaf(w0.z, v0.z, acc); acc = fmaf(w0.w, v0.w, acc);
                    acc = fmaf(w1.x, v1.x, acc); acc = fmaf(w1.y, v1.y, acc);
                    acc = fmaf(w1.z, v1.z, acc); acc = fmaf(w1.w, v1.w, acc);
                    acc = fmaf(w2.x, v2.x, acc); acc = fmaf(w2.y, v2.y, acc);
                    acc = fmaf(w2.z, v2.z, acc); acc = fmaf(w2.w, v2.w, acc);
                    acc = fmaf(w3.x, v3.x, acc); acc = fmaf(w3.y, v3.y, acc);
                    acc = fmaf(w3.z, v3.z, acc); acc = fmaf(w3.w, v3.w, acc);
                    wr += 4 * 32;
                    vv += 4 * 32;
                }
                #pragma unroll
                for (int o = 16; o > 0; o >>= 1)
                    acc += __shfl_down_sync(0xFFFFFFFFu, acc, o);
                if (lane == 0) g_sV[row] = acc;
            }
        } else {
            // ---- P / P_hat tile: 32 rows x 1024 cols ----
            const float* mat = (type == 1) ? P : Ph;
            float* o_        = (type == 1) ? g_pP : g_pPh;

            const int col = (idx & 1) * 1024 + tid * 4;
            const int r0  = (idx >> 1) * 32;

            const float4* m  = reinterpret_cast<const float4*>(mat + (size_t)r0 * K + col);
            const float4* p4 = reinterpret_cast<const float4*>(pi + r0);
            const size_t  s4 = (size_t)K / 4;

            float4 acc = make_float4(0.f, 0.f, 0.f, 0.f);
            #pragma unroll 1
            for (int rr = 0; rr < 32; rr += 8) {
                float4 w0 = __ldcs(m + 0 * s4);
                float4 w1 = __ldcs(m + 1 * s4);
                float4 w2 = __ldcs(m + 2 * s4);
                float4 w3 = __ldcs(m + 3 * s4);
                float4 w4 = __ldcs(m + 4 * s4);
                float4 w5 = __ldcs(m + 5 * s4);
                float4 w6 = __ldcs(m + 6 * s4);
                float4 w7 = __ldcs(m + 7 * s4);
                float4 pa = __ldg(p4 + 0);
                float4 pb = __ldg(p4 + 1);

                acc.x = fmaf(pa.x, w0.x, acc.x); acc.y = fmaf(pa.x, w0.y, acc.y);
                acc.z = fmaf(pa.x, w0.z, acc.z); acc.w = fmaf(pa.x, w0.w, acc.w);
                acc.x = fmaf(pa.y, w1.x, acc.x); acc.y = fmaf(pa.y, w1.y, acc.y);
                acc.z = fmaf(pa.y, w1.z, acc.z); acc.w = fmaf(pa.y, w1.w, acc.w);
                acc.x = fmaf(pa.z, w2.x, acc.x); acc.y = fmaf(pa.z, w2.y, acc.y);
                acc.z = fmaf(pa.z, w2.z, acc.z); acc.w = fmaf(pa.z, w2.w, acc.w);
                acc.x = fmaf(pa.w, w3.x, acc.x); acc.y = fmaf(pa.w, w3.y, acc.y);
                acc.z = fmaf(pa.w, w3.z, acc.z); acc.w = fmaf(pa.w, w3.w, acc.w);
                acc.x = fmaf(pb.x, w4.x, acc.x); acc.y = fmaf(pb.x, w4.y, acc.y);
                acc.z = fmaf(pb.x, w4.z, acc.z); acc.w = fmaf(pb.x, w4.w, acc.w);
                acc.x = fmaf(pb.y, w5.x, acc.x); acc.y = fmaf(pb.y, w5.y, acc.y);
                acc.z = fmaf(pb.y, w5.z, acc.z); acc.w = fmaf(pb.y, w5.w, acc.w);
                acc.x = fmaf(pb.z, w6.x, acc.x); acc.y = fmaf(pb.z, w6.y, acc.y);
                acc.z = fmaf(pb.z, w6.z, acc.z); acc.w = fmaf(pb.z, w6.w, acc.w);
                acc.x = fmaf(pb.w, w7.x, acc.x); acc.y = fmaf(pb.w, w7.y, acc.y);
                acc.z = fmaf(pb.w, w7.z, acc.z); acc.w = fmaf(pb.w, w7.w, acc.w);

                m  += 8 * s4;
                p4 += 2;
            }
            atomicAdd(&o_[col + 0], acc.x);
            atomicAdd(&o_[col + 1], acc.y);
            atomicAdd(&o_[col + 2], acc.z);
            atomicAdd(&o_[col + 3], acc.w);
        }
    }

    // ---------------- signal matvec completion (race-safe) ----------------
    __syncthreads();               // all warps of this block done with stores
    __threadfence();
    if (tid == 0) atomicAdd(&g_done, 1u);
    if (b >= EPI_BLOCKS) return;

    // ======== epilogue blocks (b in [0, EPI_BLOCKS)) ========
    // Rank precompute (depends only on L/U) — hidden in the finish spread.
    const int sliceLen   = (N + EPI_BLOCKS - 1) / EPI_BLOCKS;   // 64 @ N=4096
    const int sliceStart = b * sliceLen;

    int pre = 0;
    for (int i = tid; i < sliceStart; i += 256) {
        float li = __ldg(L + i), ui = __ldg(U + i);
        pre += (li < 0.0f && ui > 0.0f);
    }
    #pragma unroll
    for (int o = 16; o > 0; o >>= 1)
        pre += __shfl_down_sync(0xFFFFFFFFu, pre, o);
    __shared__ int wsum[8];
    __shared__ int wcnt[8];
    if (lane == 0) wsum[warp] = pre;
    if (tid < 8) wcnt[tid] = 0;
    __syncthreads();

    const int n = sliceStart + tid;          // one neuron per thread (tid<64)
    float l = 0.f, u = 0.f, c = 0.f;
    bool un = false;
    const bool active = (tid < sliceLen) && (n < N);
    if (active) {
        l = __ldg(L + n); u = __ldg(U + n); c = __ldg(C + n);
        un = (l < 0.0f) && (u > 0.0f);
    }
    unsigned bm = __ballot_sync(0xFFFFFFFFu, un);
    int before = __popc(bm & ((1u << lane) - 1u));
    if (lane == 0) wcnt[warp] = __popc(bm);
    __syncthreads();

    int prefix = 0;
    #pragma unroll
    for (int w = 0; w < 8; ++w) prefix += wsum[w];
    int woff = 0, totalCnt = 0;
    #pragma unroll
    for (int w = 0; w < 8; ++w) {
        woff     += (w < warp) ? wcnt[w] : 0;
        totalCnt += wcnt[w];
    }
    const int k = prefix + woff + before;
    float a_k = 0.0f;
    if (active && un && k < K) a_k = __ldg(alpha + k);

    // ---------------- wait for ALL blocks ----------------
    if (tid == 0) {
        while (atomicAdd(&g_done, 0u) < (unsigned)GRID) __nanosleep(32);
    }
    __syncthreads();
    __threadfence();

    // ---------------- elementwise epilogue (L2-hot) ----------------
    if (active) {
        float val;
        if (un) {
            if (k < K) {
                float vhat = g_sV[n] - g_pPh[k];
                float rp   = fmaxf(vhat, 0.0f);
                float rn   = fmaxf(-vhat, 0.0f);
                val = rp * u / (u - l) - c - a_k * rn - g_pP[k];
            } else {
                val = 0.0f;
            }
        } else if (u <= 0.0f) {
            val = -c;                  // stably deactivated (sV never needed)
        } else if (l >= 0.0f) {
            val = g_sV[n] - c;         // stably activated
        } else {
            val = 0.0f;
        }
        out[n] = val;
    }

    // ---------------- reset scratch for next graph replay ----------------
    __syncthreads();
    const int zEnd = (b == EPI_BLOCKS - 1) ? K : (prefix + totalCnt);
    for (int i = prefix + tid; i < zEnd; i += 256) {
        g_pP[i]  = 0.0f;
        g_pPh[i] = 0.0f;
    }
    __threadfence();
    if (tid == 0) {
        unsigned d2 = atomicAdd(&g_done2, 1u);
        if (d2 == EPI_BLOCKS - 1) {   // very last epilogue block resets counters
            g_done  = 0;
            g_done2 = 0;
            __threadfence();
        }
    }
}

extern "C" void kernel_launch(void* const* d_in, const int* in_sizes, int n_in,
                              void* d_out, int out_size) {
    const float* Vn    = (const float*)d_in[0];   // [N_NEXT]
    const float* W     = (const float*)d_in[1];   // [N_NEXT, N]
    const float* C     = (const float*)d_in[2];   // [N]
    const float* L     = (const float*)d_in[3];   // [N]
    const float* U     = (const float*)d_in[4];   // [N]
    const float* P     = (const float*)d_in[5];   // [P_ROWS, K]
    const float* Ph    = (const float*)d_in[6];   // [P_ROWS, K]
    const float* pi    = (const float*)d_in[7];   // [P_ROWS]
    const float* alpha = (const float*)d_in[8];   // [K]
    float* out = (float*)d_out;

    const int Nnext = in_sizes[0];
    const int N     = in_sizes[2];
    const int Prows = in_sizes[7];
    const int K     = in_sizes[8];

    fused_kernel<<<GRID, 256>>>(W, Vn, P, Ph, pi, C, L, U, alpha, out,
                                N, Nnext, K, Prows);
}